// round 1
// baseline (speedup 1.0000x reference)
#include <cuda_runtime.h>

#define NB   4096
#define KCH  3
#define FIN  16
#define FOUT 16
#define TT   12
#define BATCH 2
#define COLS (BATCH*FOUT*TT)        /* 384 */
#define OUT_ELEMS (BATCH*NB*FOUT*TT) /* 1572864 */

__device__ float g_lhs[KCH*FIN*FOUT];            // 768
__device__ float g_z[(size_t)KCH*NB*COLS];       // 4,718,592 floats (18 MB)
__device__ float g_acc[(size_t)NB*COLS];         // 1,572,864 floats (6 MB)

// ---------------------------------------------------------------------------
// lhs[k,f,o] = 0.5 * sum_j Gamma[j,f,o] * xj[j,k]   (scale 2/(K+1) folded in)
// ---------------------------------------------------------------------------
__global__ void lhs_kernel(const float* __restrict__ Gamma,
                           const float* __restrict__ xj) {
    int idx = blockIdx.x * blockDim.x + threadIdx.x;
    if (idx < KCH*FIN*FOUT) {
        int k  = idx / (FIN*FOUT);
        int fo = idx % (FIN*FOUT);
        float s = 0.f;
#pragma unroll
        for (int j = 0; j < KCH; ++j)
            s += Gamma[j*FIN*FOUT + fo] * xj[j*KCH + k];
        g_lhs[idx] = 0.5f * s;
    }
}

// ---------------------------------------------------------------------------
// z[k][m][b*192 + o*12 + t] = sum_f x[b,m,f,t] * lhs[k,f,o]
// one block per (b,m), 192 threads = (o,t)
// ---------------------------------------------------------------------------
__global__ void z_kernel(const float* __restrict__ x) {
    __shared__ float xs[FIN*TT];          // 192
    __shared__ float ls[KCH*FIN*FOUT];    // 768
    const int bm  = blockIdx.x;           // b*NB + m
    const int tid = threadIdx.x;          // 0..191
    xs[tid] = x[(size_t)bm * (FIN*TT) + tid];
    for (int i = tid; i < KCH*FIN*FOUT; i += FIN*TT) ls[i] = g_lhs[i];
    __syncthreads();
    const int o = tid / TT, t = tid % TT;
    const int b = bm >> 12, m = bm & (NB - 1);
#pragma unroll
    for (int k = 0; k < KCH; ++k) {
        float s = 0.f;
#pragma unroll
        for (int f = 0; f < FIN; ++f)
            s += xs[f*TT + t] * ls[k*(FIN*FOUT) + f*FOUT + o];
        g_z[(size_t)k*NB*COLS + (size_t)m*COLS + b*(FOUT*TT) + o*TT + t] = s;
    }
}

// ---------------------------------------------------------------------------
// zero the accumulator scratch (vectorized)
// ---------------------------------------------------------------------------
__global__ void zero_kernel() {
    int idx = blockIdx.x * blockDim.x + threadIdx.x;  // float4 index
    if (idx < OUT_ELEMS / 4) {
        ((float4*)g_acc)[idx] = make_float4(0.f, 0.f, 0.f, 0.f);
    }
}

// ---------------------------------------------------------------------------
// packed f32x2 helpers (FFMA2 only reachable via PTX fma.rn.f32x2)
// ---------------------------------------------------------------------------
__device__ __forceinline__ unsigned long long dup2(float a) {
    unsigned long long r;
    asm("mov.b64 %0, {%1, %1};" : "=l"(r) : "r"(__float_as_uint(a)));
    return r;
}
__device__ __forceinline__ void fma2(unsigned long long& d,
                                     unsigned long long a,
                                     unsigned long long b) {
    asm("fma.rn.f32x2 %0, %1, %2, %0;" : "+l"(d) : "l"(a), "l"(b));
}

// ---------------------------------------------------------------------------
// GEMM: g_acc[n][col] += sum_m cheb[k][m][n] * g_z[k][m][col], k = blockIdx.z
// 128x128 C-tile, BK=8, 256 threads, 8x8 microtile in 4+4 split layout.
// ---------------------------------------------------------------------------
__global__ void __launch_bounds__(256) gemm_kernel(const float* __restrict__ cheb) {
    const int k  = blockIdx.z;
    const int n0 = blockIdx.y << 7;     // row block (n dim)
    const int c0 = blockIdx.x << 7;     // col block (b,o,t dim)

    __shared__ float As[8][128];
    __shared__ float Bs[8][128];

    const int tid = threadIdx.x;
    const int lr  = tid >> 5;            // 0..7  (m within tile)
    const int lc  = (tid & 31) << 2;     // 0..124

    const float* ag = cheb + (size_t)k*NB*NB  + (size_t)lr*NB   + n0 + lc;
    const float* bg = g_z  + (size_t)k*NB*COLS + (size_t)lr*COLS + c0 + lc;

    const int rt = (tid & 15) << 2;      // row base within 0..63
    const int ct = (tid >> 4) << 2;      // col base within 0..63

    unsigned long long acc[8][4];
#pragma unroll
    for (int i = 0; i < 8; ++i)
#pragma unroll
        for (int j = 0; j < 4; ++j) acc[i][j] = 0ULL;

    float4 aN = *(const float4*)ag;
    float4 bN = *(const float4*)bg;

    for (int step = 0; step < NB/8; ++step) {
        *(float4*)&As[lr][lc] = aN;
        *(float4*)&Bs[lr][lc] = bN;
        __syncthreads();
        if (step + 1 < NB/8) {
            aN = *(const float4*)(ag + (size_t)(step + 1) * 8 * NB);
            bN = *(const float4*)(bg + (size_t)(step + 1) * 8 * COLS);
        }
#pragma unroll
        for (int kk = 0; kk < 8; ++kk) {
            float4 a0 = *(const float4*)&As[kk][rt];
            float4 a1 = *(const float4*)&As[kk][rt + 64];
            unsigned long long b0 = *(const unsigned long long*)&Bs[kk][ct];
            unsigned long long b1 = *(const unsigned long long*)&Bs[kk][ct + 2];
            unsigned long long b2 = *(const unsigned long long*)&Bs[kk][ct + 64];
            unsigned long long b3 = *(const unsigned long long*)&Bs[kk][ct + 66];
            unsigned long long ad[8];
            ad[0] = dup2(a0.x); ad[1] = dup2(a0.y);
            ad[2] = dup2(a0.z); ad[3] = dup2(a0.w);
            ad[4] = dup2(a1.x); ad[5] = dup2(a1.y);
            ad[6] = dup2(a1.z); ad[7] = dup2(a1.w);
#pragma unroll
            for (int i = 0; i < 8; ++i) {
                fma2(acc[i][0], ad[i], b0);
                fma2(acc[i][1], ad[i], b1);
                fma2(acc[i][2], ad[i], b2);
                fma2(acc[i][3], ad[i], b3);
            }
        }
        __syncthreads();
    }

    // accumulate across the 3 k-batches
#pragma unroll
    for (int i = 0; i < 8; ++i) {
        int row = n0 + ((i < 4) ? (rt + i) : (64 + rt + (i - 4)));
#pragma unroll
        for (int j = 0; j < 4; ++j) {
            int col = c0 + ((j < 2) ? (ct + 2*j) : (64 + ct + 2*(j - 2)));
            float2 v = *(float2*)&acc[i][j];
            atomicAdd(&g_acc[(size_t)row*COLS + col],     v.x);
            atomicAdd(&g_acc[(size_t)row*COLS + col + 1], v.y);
        }
    }
}

// ---------------------------------------------------------------------------
// out[b,n,o,t] = relu(g_acc[n][b*192 + o*12 + t])   (0.5 already folded in)
// ---------------------------------------------------------------------------
__global__ void relu_kernel(float* __restrict__ out) {
    int idx = blockIdx.x * blockDim.x + threadIdx.x;
    if (idx < OUT_ELEMS) {
        int b = idx / (NB * FOUT * TT);
        int r = idx % (NB * FOUT * TT);
        int n = r / (FOUT * TT);
        int c = r % (FOUT * TT);
        float v = g_acc[(size_t)n * COLS + b * (FOUT * TT) + c];
        out[idx] = fmaxf(v, 0.f);
    }
}

// ---------------------------------------------------------------------------
extern "C" void kernel_launch(void* const* d_in, const int* in_sizes, int n_in,
                              void* d_out, int out_size) {
    const float* x     = (const float*)d_in[0];  // (2,4096,16,12)
    const float* cheb  = (const float*)d_in[1];  // (3,4096,4096)
    const float* xj    = (const float*)d_in[2];  // (3,3)
    const float* Gamma = (const float*)d_in[3];  // (3,16,16)
    float* out = (float*)d_out;

    lhs_kernel<<<3, 256>>>(Gamma, xj);
    zero_kernel<<<(OUT_ELEMS/4 + 255) / 256, 256>>>();
    z_kernel<<<BATCH * NB, FIN * TT>>>(x);

    dim3 grid(COLS / 128, NB / 128, KCH);   // (3, 32, 3) = 288 blocks
    gemm_kernel<<<grid, 256>>>(cheb);

    relu_kernel<<<(OUT_ELEMS + 255) / 256, 256>>>(out);
}

// round 3
// speedup vs baseline: 3.0596x; 3.0596x over previous
#include <cuda_runtime.h>
#include <cstdint>

#define NB    4096
#define KCH   3
#define FIN   16
#define FOUT  16
#define TT    12
#define BATCH 2
#define COLS  384                       /* BATCH*FOUT*TT */
#define OUT_ELEMS (BATCH*NB*FOUT*TT)    /* 1572864 */

#define BM 128
#define BN 128
#define BKK 32
#define A_PAD 136
#define B_PAD 36
#define AS_FLOATS (BKK*A_PAD)                 /* 4352 */
#define BS_FLOATS (BN*B_PAD)                  /* 4608 */
#define STAGE_FLOATS (AS_FLOATS + BS_FLOATS)  /* 8960 -> 35840 B */
#define SMEM_BYTES (2*STAGE_FLOATS*4)         /* 71680 */

__device__ float g_lhs[KCH*FIN*FOUT];
__device__ float g_zT[(size_t)KCH*COLS*NB];     // [k][col][m], m contiguous (tf32-rounded)
__device__ float g_part[(size_t)KCH*NB*COLS];   // [k][n][col]

// ---------------------------------------------------------------------------
__device__ __forceinline__ uint32_t smem_u32(const void* p) {
    uint32_t a;
    asm("{ .reg .u64 t; cvta.to.shared.u64 t, %1; cvt.u32.u64 %0, t; }" : "=r"(a) : "l"(p));
    return a;
}
#define CPASYNC16(d, s) asm volatile("cp.async.cg.shared.global [%0], [%1], 16;" :: "r"(d), "l"(s) : "memory")
#define CP_COMMIT()     asm volatile("cp.async.commit_group;" ::: "memory")

__device__ __forceinline__ void mma_tf32(float* c, const uint32_t* a, const uint32_t* b) {
    asm volatile(
        "mma.sync.aligned.m16n8k8.row.col.f32.tf32.tf32.f32 "
        "{%0,%1,%2,%3}, {%4,%5,%6,%7}, {%8,%9}, {%0,%1,%2,%3};"
        : "+f"(c[0]), "+f"(c[1]), "+f"(c[2]), "+f"(c[3])
        : "r"(a[0]), "r"(a[1]), "r"(a[2]), "r"(a[3]), "r"(b[0]), "r"(b[1]));
}
__device__ __forceinline__ uint32_t to_tf32(float f) {
    uint32_t u; asm("cvt.rna.tf32.f32 %0, %1;" : "=r"(u) : "f"(f)); return u;
}

// ---------------------------------------------------------------------------
// lhs[k,f,o] = 0.5 * sum_j Gamma[j,f,o] * xj[j,k]
// ---------------------------------------------------------------------------
__global__ void lhs_kernel(const float* __restrict__ Gamma, const float* __restrict__ xj) {
    int idx = blockIdx.x * blockDim.x + threadIdx.x;
    if (idx < KCH*FIN*FOUT) {
        int k = idx / (FIN*FOUT), fo = idx % (FIN*FOUT);
        float s = 0.f;
#pragma unroll
        for (int j = 0; j < KCH; ++j) s += Gamma[j*FIN*FOUT + fo] * xj[j*KCH + k];
        g_lhs[idx] = 0.5f * s;
    }
}

// ---------------------------------------------------------------------------
// zT[k][col=b*192+o*12+t][m] = rn_tf32( sum_f x[b,m,f,t] * lhs[k,f,o] )
// ---------------------------------------------------------------------------
__global__ void zT_kernel(const float* __restrict__ x) {
    __shared__ float ls[KCH*FIN*FOUT];
    const int tid = threadIdx.x;
    const int mc = blockIdx.x, t = blockIdx.y, b = blockIdx.z;
    for (int i = tid; i < KCH*FIN*FOUT; i += 128) ls[i] = g_lhs[i];
    __syncthreads();
    const int m = mc * 128 + tid;
    float xv[FIN];
    const float* xp = x + ((size_t)(b*NB + m) * FIN) * TT + t;
#pragma unroll
    for (int f = 0; f < FIN; ++f) xv[f] = xp[f*TT];
#pragma unroll
    for (int k = 0; k < KCH; ++k)
#pragma unroll
        for (int o = 0; o < FOUT; ++o) {
            float s = 0.f;
#pragma unroll
            for (int f = 0; f < FIN; ++f) s += xv[f] * ls[(k*FIN + f)*FOUT + o];
            g_zT[((size_t)k*COLS + b*(FOUT*TT) + o*TT + t) * NB + m] = __uint_as_float(to_tf32(s));
        }
}

// ---------------------------------------------------------------------------
// GEMM: g_part[kb][n][col] = sum_m cheb[kb][m][n] * zT[kb][col][m]
// mma.sync tf32, 128x128x32 tiles, double-buffered cp.async
// ---------------------------------------------------------------------------
__global__ void __launch_bounds__(256, 2) gemm_kernel(const float* __restrict__ cheb) {
    extern __shared__ float sm[];
    const int tid  = threadIdx.x;
    const int lane = tid & 31, wid = tid >> 5;
    const int warp_m = wid >> 1, warp_n = wid & 1;
    const int n0 = blockIdx.x * BM;
    const int c0 = blockIdx.y * BN;
    const int kb = blockIdx.z;

    const float* Ag = cheb + (size_t)kb*NB*NB + n0;              // + m*NB
    const float* Bg = g_zT + (size_t)kb*COLS*NB + (size_t)c0*NB; // + col*NB + m

    // ---- stage loader: A[m][n] rows (32 x 128), B[col][m] rows (128 x 32)
    auto load_stage = [&](int stage, int m0) {
        float* As = sm + stage * STAGE_FLOATS;
        float* Bs = As + AS_FLOATS;
#pragma unroll
        for (int j = 0; j < 4; ++j) {
            int i = tid + 256*j;
            int m = i >> 5, c = i & 31;
            CPASYNC16(smem_u32(As + m*A_PAD + c*4), Ag + (size_t)(m0 + m)*NB + c*4);
        }
#pragma unroll
        for (int j = 0; j < 4; ++j) {
            int i = tid + 256*j;
            int col = i >> 3, c = i & 7;
            CPASYNC16(smem_u32(Bs + col*B_PAD + c*4), Bg + (size_t)col*NB + m0 + c*4);
        }
    };

    load_stage(0, 0);   CP_COMMIT();
    load_stage(1, BKK); CP_COMMIT();

    float acc[2][8][4];
#pragma unroll
    for (int mi = 0; mi < 2; ++mi)
#pragma unroll
        for (int ni = 0; ni < 8; ++ni)
#pragma unroll
            for (int q = 0; q < 4; ++q) acc[mi][ni][q] = 0.f;

    const int nb0 = warp_m * 32;
    const int cb0 = warp_n * 64;
    const int r4  = lane >> 2;   // 0..7
    const int l4  = lane & 3;    // 0..3

    for (int it = 0; it < NB/BKK; ++it) {
        asm volatile("cp.async.wait_group 1;" ::: "memory");
        __syncthreads();
        const float* As = sm + (it & 1) * STAGE_FLOATS;
        const float* Bs = As + AS_FLOATS;
#pragma unroll
        for (int ks = 0; ks < 4; ++ks) {
            const int kk = ks * 8;
            uint32_t a[2][4];
#pragma unroll
            for (int mi = 0; mi < 2; ++mi) {
                const int nb = nb0 + mi*16 + r4;
                const int mm = kk + l4;
                a[mi][0] = to_tf32(As[ mm      *A_PAD + nb    ]);
                a[mi][1] = to_tf32(As[ mm      *A_PAD + nb + 8]);
                a[mi][2] = to_tf32(As[(mm + 4) *A_PAD + nb    ]);
                a[mi][3] = to_tf32(As[(mm + 4) *A_PAD + nb + 8]);
            }
            uint32_t b[8][2];
#pragma unroll
            for (int ni = 0; ni < 8; ++ni) {
                const int cc = cb0 + ni*8 + r4;
                const int mm = kk + l4;
                b[ni][0] = __float_as_uint(Bs[cc*B_PAD + mm    ]);
                b[ni][1] = __float_as_uint(Bs[cc*B_PAD + mm + 4]);
            }
#pragma unroll
            for (int mi = 0; mi < 2; ++mi)
#pragma unroll
                for (int ni = 0; ni < 8; ++ni)
                    mma_tf32(acc[mi][ni], a[mi], b[ni]);
        }
        __syncthreads();
        if (it + 2 < NB/BKK) load_stage(it & 1, (it + 2) * BKK);
        CP_COMMIT();
    }

    // ---- epilogue: per-k partials
    float* P = g_part + (size_t)kb*NB*COLS;
#pragma unroll
    for (int mi = 0; mi < 2; ++mi) {
        const int row0 = n0 + nb0 + mi*16 + r4;
#pragma unroll
        for (int ni = 0; ni < 8; ++ni) {
            const int col = c0 + cb0 + ni*8 + 2*l4;
            *(float2*)&P[(size_t) row0      *COLS + col] = make_float2(acc[mi][ni][0], acc[mi][ni][1]);
            *(float2*)&P[(size_t)(row0 + 8) *COLS + col] = make_float2(acc[mi][ni][2], acc[mi][ni][3]);
        }
    }
}

// ---------------------------------------------------------------------------
// out[b,n,o,t] = relu( sum_kb g_part[kb][n][b*192 + o*12 + t] )
// ---------------------------------------------------------------------------
__global__ void relu_sum_kernel(float* __restrict__ out) {
    int idx = blockIdx.x * blockDim.x + threadIdx.x;
    if (idx < OUT_ELEMS) {
        int b = idx / (NB*FOUT*TT);
        int r = idx % (NB*FOUT*TT);
        int n = r / (FOUT*TT);
        int c = r % (FOUT*TT);
        size_t p = (size_t)n*COLS + b*(FOUT*TT) + c;
        float v = g_part[p] + g_part[(size_t)NB*COLS + p] + g_part[2*(size_t)NB*COLS + p];
        out[idx] = fmaxf(v, 0.f);
    }
}

// ---------------------------------------------------------------------------
extern "C" void kernel_launch(void* const* d_in, const int* in_sizes, int n_in,
                              void* d_out, int out_size) {
    const float* x     = (const float*)d_in[0];
    const float* cheb  = (const float*)d_in[1];
    const float* xj    = (const float*)d_in[2];
    const float* Gamma = (const float*)d_in[3];
    float* out = (float*)d_out;

    cudaFuncSetAttribute(gemm_kernel, cudaFuncAttributeMaxDynamicSharedMemorySize, SMEM_BYTES);

    lhs_kernel<<<3, 256>>>(Gamma, xj);
    zT_kernel<<<dim3(32, 12, 2), 128>>>(x);
    gemm_kernel<<<dim3(32, 3, 3), 256, SMEM_BYTES>>>(cheb);
    relu_sum_kernel<<<(OUT_ELEMS + 255)/256, 256>>>(out);
}